// round 16
// baseline (speedup 1.0000x reference)
#include <cuda_runtime.h>
#include <cuda_bf16.h>
#include <math.h>
#include <stdint.h>

// ---------------- problem constants ----------------
#define B_    64
#define C_    256
#define NPIX  2304          // 48*48
#define BN_TOT (B_ * NPIX)  // 147456 pixels
#define NH_   8
#define DH_   32
#define M_    64
#define DFF_  512

// ---------------- scratch (__device__ globals; no allocs allowed) ----------------
__device__ float    g_kp[C_ * M_];
__device__ float    g_vp[C_ * M_];
__device__ uint32_t g_Xpk [(size_t)C_  * BN_TOT];   // packed split-bf16 (hi | lo<<16)
__device__ uint32_t g_Opk [(size_t)C_  * BN_TOT];
__device__ uint32_t g_H1pk[(size_t)DFF_ * BN_TOT];
// pre-split+tiled weights: per (rowtile rt of 256, kchunk kc of 16):
//   12288 bf16 = hi[256 rows x 24 (16 used)] | lo[same]; rows 48B
__device__ __align__(16) __nv_bfloat16 g_wqb[(size_t)1 * 16 * 12288];
__device__ __align__(16) __nv_bfloat16 g_wmb[(size_t)1 * 16 * 12288];
__device__ __align__(16) __nv_bfloat16 g_w1b[(size_t)2 * 16 * 12288];
__device__ __align__(16) __nv_bfloat16 g_w2b[(size_t)1 * 32 * 12288];

// ---------------- helpers ----------------
__device__ __forceinline__ float fast_exp(float x) {
    x = fmaxf(x, -80.0f);
    float y  = x * 1.4426950408889634f;
    float fk = floorf(y);
    float f  = y - fk;
    float p  = 1.5398e-4f;
    p = fmaf(p, f, 1.3333558e-3f);
    p = fmaf(p, f, 9.6181291e-3f);
    p = fmaf(p, f, 5.5504109e-2f);
    p = fmaf(p, f, 2.4022651e-1f);
    p = fmaf(p, f, 6.9314718e-1f);
    p = fmaf(p, f, 1.0f);
    return __int_as_float(((int)fk + 127) << 23) * p;
}
__device__ __forceinline__ uint32_t pack_split(float v) {
    __nv_bfloat16 h = __float2bfloat16(v);
    __nv_bfloat16 l = __float2bfloat16(v - __bfloat162float(h));
    return (uint32_t)__bfloat16_as_ushort(h) | ((uint32_t)__bfloat16_as_ushort(l) << 16);
}
__device__ __forceinline__ float unpack_f(uint32_t p) {
    return __bfloat162float(__ushort_as_bfloat16((unsigned short)(p & 0xffffu))) +
           __bfloat162float(__ushort_as_bfloat16((unsigned short)(p >> 16)));
}
__device__ __forceinline__ void mma_bf16(float* d, const uint32_t* a, const uint32_t* b) {
    asm volatile("mma.sync.aligned.m16n8k16.row.col.f32.bf16.bf16.f32 "
        "{%0,%1,%2,%3}, {%4,%5,%6,%7}, {%8,%9}, {%0,%1,%2,%3};"
        : "+f"(d[0]), "+f"(d[1]), "+f"(d[2]), "+f"(d[3])
        : "r"(a[0]), "r"(a[1]), "r"(a[2]), "r"(a[3]), "r"(b[0]), "r"(b[1]));
}
__device__ __forceinline__ void ldsm4(uint32_t* r, uint32_t addr) {
    asm volatile("ldmatrix.sync.aligned.m8n8.x4.shared.b16 {%0,%1,%2,%3}, [%4];"
        : "=r"(r[0]), "=r"(r[1]), "=r"(r[2]), "=r"(r[3]) : "r"(addr));
}
__device__ __forceinline__ void ldsm2(uint32_t* r, uint32_t addr) {
    asm volatile("ldmatrix.sync.aligned.m8n8.x2.shared.b16 {%0,%1}, [%2];"
        : "=r"(r[0]), "=r"(r[1]) : "r"(addr));
}
__device__ __forceinline__ void cp16(uint32_t dst, const void* src) {
    asm volatile("cp.async.cg.shared.global [%0], [%1], 16;" :: "r"(dst), "l"(src) : "memory");
}
#define CP_COMMIT() asm volatile("cp.async.commit_group;" ::: "memory")
#define CP_WAIT(n)  asm volatile("cp.async.wait_group %0;" :: "n"(n) : "memory")

// ---------------- weight split/tiling prep ----------------
__global__ void wsplit(const float* __restrict__ W, __nv_bfloat16* __restrict__ dst,
                       int R, int K)
{
    int e = blockIdx.x * 256 + threadIdx.x;
    if (e >= R * K) return;
    int r = e / K, k = e - r * K;
    float v = W[e];
    int rt = r >> 8, rr = r & 255, kc = k >> 4, kk = k & 15;
    size_t base = (size_t)(rt * (K >> 4) + kc) * 12288 + rr * 24 + kk;
    __nv_bfloat16 h = __float2bfloat16(v);
    dst[base]        = h;
    dst[base + 6144] = __float2bfloat16(v - __bfloat162float(h));
}

// ---------------- K/V projections (batch-invariant, tiny) ----------------
__global__ void kv_proj(const float* __restrict__ wk, const float* __restrict__ bk,
                        const float* __restrict__ wv, const float* __restrict__ bv,
                        const float* __restrict__ bcw)
{
    __shared__ float bs[C_];
    int m = blockIdx.x, o = threadIdx.x;
    bs[o] = bcw[m * C_ + o];
    __syncthreads();
    float ak = bk[o], av = bv[o];
    const float* wkr = wk + (size_t)o * C_;
    const float* wvr = wv + (size_t)o * C_;
#pragma unroll 8
    for (int c = 0; c < C_; c++) {
        ak = fmaf(wkr[c], bs[c], ak);
        av = fmaf(wvr[c], bs[c], av);
    }
    g_kp[o * M_ + m] = ak;
    g_vp[o * M_ + m] = av;
}

// ---------------- pipelined HMMA split-bf16 GEMM, 256 rows x 64 px tile ----------------
// EPI: 0 = bias(+relu) -> packed u32.     1 = bias + fused cosine reweight -> packed O.
//      2 = bias + resid(packed) + LayerNorm -> fp32 final out.
//      3 = bias + fused attention (per-thread softmax, validated algorithm) -> packed X.
template<int EPI, int AF32>
__global__ __launch_bounds__(256, 2)
void hgemm(const __nv_bfloat16* __restrict__ wblk, const void* __restrict__ Xv,
           const float* __restrict__ bias,
           const float* __restrict__ feat,       // EPI==1
           const uint32_t* __restrict__ respk,   // EPI==2
           const float* __restrict__ gamma, const float* __restrict__ beta,  // EPI==2
           void* __restrict__ Yv, int R, int K, int act)
{
    extern __shared__ char sm[];
    const int tid  = threadIdx.x;
    const int lane = tid & 31, wid = tid >> 5;
    const int wm = wid & 3, wn = wid >> 2;
    const int n0g = blockIdx.x * 64;
    const int b   = n0g / NPIX;
    const int nn  = n0g - b * NPIX;
    const int rt  = blockIdx.y;
    const int NCH = K >> 4;
    const uint32_t sb = (uint32_t)__cvta_generic_to_shared(sm);
    const char* Xb = (const char*)Xv + ((size_t)b * K * NPIX + nn) * 4;

    float acc[4][4][4];
#pragma unroll
    for (int i = 0; i < 4; i++)
#pragma unroll
        for (int j = 0; j < 4; j++)
#pragma unroll
            for (int q = 0; q < 4; q++) acc[i][j][q] = 0.0f;

    auto load_chunk = [&](int kc) {
        const int s = kc % 3;
        const uint4* ws = (const uint4*)(wblk + (size_t)(rt * NCH + kc) * 12288);
        const uint32_t wdst = sb + s * 24576;
#pragma unroll
        for (int j = 0; j < 6; j++)
            cp16(wdst + (tid + j * 256) * 16, ws + tid + j * 256);
        const uint32_t sdst = sb + 73728 + s * 4096;
        cp16(sdst + tid * 16,
             Xb + ((size_t)(kc * 16 + (tid >> 4)) * NPIX + (tid & 15) * 4) * 4);
        CP_COMMIT();
    };

    auto convert = [&](int kc) {
        const int s = kc % 3;
        const char* stg = sm + 73728 + s * 4096;
        char* pl = sm + 86016 + (kc & 1) * 6144;
        const int px = tid & 63, kseg = tid >> 6;
        uint32_t hv[2], lv[2];
        if (AF32) {
            const float* st = (const float*)stg;
#pragma unroll
            for (int t = 0; t < 2; t++) {
                float v0 = st[(kseg * 4 + 2 * t    ) * 64 + px];
                float v1 = st[(kseg * 4 + 2 * t + 1) * 64 + px];
                __nv_bfloat16 h0 = __float2bfloat16(v0), h1 = __float2bfloat16(v1);
                __nv_bfloat16 l0 = __float2bfloat16(v0 - __bfloat162float(h0));
                __nv_bfloat16 l1 = __float2bfloat16(v1 - __bfloat162float(h1));
                hv[t] = (uint32_t)__bfloat16_as_ushort(h0) | ((uint32_t)__bfloat16_as_ushort(h1) << 16);
                lv[t] = (uint32_t)__bfloat16_as_ushort(l0) | ((uint32_t)__bfloat16_as_ushort(l1) << 16);
            }
        } else {
            const uint32_t* st = (const uint32_t*)stg;
#pragma unroll
            for (int t = 0; t < 2; t++) {
                uint32_t w0 = st[(kseg * 4 + 2 * t    ) * 64 + px];
                uint32_t w1 = st[(kseg * 4 + 2 * t + 1) * 64 + px];
                hv[t] = (w0 & 0xffffu) | (w1 << 16);
                lv[t] = (w0 >> 16)     | (w1 & 0xffff0000u);
            }
        }
        *(uint2*)(pl +        px * 48 + kseg * 8) = make_uint2(hv[0], hv[1]);
        *(uint2*)(pl + 3072 + px * 48 + kseg * 8) = make_uint2(lv[0], lv[1]);
    };

    auto do_mma = [&](int kc) {
        const uint32_t sbW = sb + (kc % 3) * 24576;
        const uint32_t sbX = sb + 86016 + (kc & 1) * 6144;
        uint32_t bh[4][2], bl[4][2];
#pragma unroll
        for (int nt = 0; nt < 4; nt++) {
            int rowB = wn * 32 + nt * 8 + (lane & 7);
            uint32_t ab = sbX + rowB * 48 + ((lane >> 3) & 1) * 16;
            ldsm2(bh[nt], ab);
            ldsm2(bl[nt], ab + 3072);
        }
#pragma unroll
        for (int mt = 0; mt < 4; mt++) {
            int rowA = wm * 64 + mt * 16 + (lane & 7) + ((lane >> 3) & 1) * 8;
            uint32_t aa = sbW + rowA * 48 + (lane >> 4) * 16;
            uint32_t ah[4], al[4];
            ldsm4(ah, aa);
            ldsm4(al, aa + 12288);
#pragma unroll
            for (int nt = 0; nt < 4; nt++) {
                mma_bf16(acc[mt][nt], ah, bh[nt]);
                mma_bf16(acc[mt][nt], ah, bl[nt]);
                mma_bf16(acc[mt][nt], al, bh[nt]);
            }
        }
    };

    load_chunk(0);
    load_chunk(1);
    CP_WAIT(1);
    __syncthreads();
    convert(0);
    for (int kc = 0; kc < NCH; kc++) {
        __syncthreads();
        if (kc + 2 < NCH) load_chunk(kc + 2);
        do_mma(kc);
        if (kc + 1 < NCH) convert(kc + 1);
        CP_WAIT(0);
    }

    const int g = lane >> 2, q = lane & 3;

    if (EPI == 0) {
        uint32_t* Y = (uint32_t*)Yv;
#pragma unroll
        for (int mt = 0; mt < 4; mt++) {
            int r0 = rt * 256 + wm * 64 + mt * 16 + g;
            float b0v = __ldg(bias + r0), b1v = __ldg(bias + r0 + 8);
#pragma unroll
            for (int nt = 0; nt < 4; nt++) {
                int px0 = nn + wn * 32 + nt * 8 + 2 * q;
                size_t off0 = ((size_t)b * R + r0) * NPIX + px0;
                size_t off1 = off0 + (size_t)8 * NPIX;
                float v0 = acc[mt][nt][0] + b0v, v1 = acc[mt][nt][1] + b0v;
                float v2 = acc[mt][nt][2] + b1v, v3 = acc[mt][nt][3] + b1v;
                if (act) {
                    v0 = fmaxf(v0, 0.f); v1 = fmaxf(v1, 0.f);
                    v2 = fmaxf(v2, 0.f); v3 = fmaxf(v3, 0.f);
                }
                *(uint2*)(Y + off0) = make_uint2(pack_split(v0), pack_split(v1));
                *(uint2*)(Y + off1) = make_uint2(pack_split(v2), pack_split(v3));
            }
        }
        return;
    }

    // ---- fused epilogues (R == 256, rt == 0): smem reuse after mainloop
    __syncthreads();
    float* sV = (float*)sm;                      // [256 c][64 px]

#pragma unroll
    for (int mt = 0; mt < 4; mt++) {
        int c0 = wm * 64 + mt * 16 + g;
        float b0v = __ldg(bias + c0), b1v = __ldg(bias + c0 + 8);
#pragma unroll
        for (int nt = 0; nt < 4; nt++) {
            int px0 = wn * 32 + nt * 8 + 2 * q;
            sV[c0 * 64 + px0]           = acc[mt][nt][0] + b0v;
            sV[c0 * 64 + px0 + 1]       = acc[mt][nt][1] + b0v;
            sV[(c0 + 8) * 64 + px0]     = acc[mt][nt][2] + b1v;
            sV[(c0 + 8) * 64 + px0 + 1] = acc[mt][nt][3] + b1v;
        }
    }
    __syncthreads();

    const int px = tid & 63, cseg = tid >> 6;

    if (EPI == 3) {
        // ---- fused attention: per-thread full softmax (validated standalone algorithm),
        // thread = (pixel px, head-group cseg); heads 4 at a time; K then V staged in smem.
        float* kvs = (float*)(sm + 65536);        // [4 heads][32 d][64 m] fp32 = 32768 B
        uint32_t* Y = (uint32_t*)Yv;
        const float scl = 0.17677669529663687f;   // 1/sqrt(32)

#pragma unroll 1
        for (int hb = 0; hb < NH_; hb += 4) {
            const int h = hb + cseg;
            // stage K for heads hb..hb+3 (coalesced over m)
            for (int i = tid; i < 4 * DH_ * M_; i += 256) {
                int gg = i >> 11, d = (i >> 6) & 31, m = i & 63;
                kvs[i] = g_kp[(d * NH_ + hb + gg) * M_ + m];
            }
            __syncthreads();

            // scores (q from sV, k broadcast from smem) — all per-thread
            const float* kh = kvs + cseg * (DH_ * M_);
            float s[M_];
#pragma unroll
            for (int m = 0; m < M_; m++) s[m] = 0.0f;
#pragma unroll 2
            for (int d = 0; d < DH_; d++) {
                float qv = sV[(d * NH_ + h) * 64 + px];
                const float* kr = kh + d * M_;
#pragma unroll
                for (int m = 0; m < M_; m++) s[m] = fmaf(qv, kr[m], s[m]);
            }
            float mx = s[0];
#pragma unroll
            for (int m = 1; m < M_; m++) mx = fmaxf(mx, s[m]);
            float ssum = 0.0f;
#pragma unroll
            for (int m = 0; m < M_; m++) {
                float e = fast_exp((s[m] - mx) * scl);
                s[m] = e;
                ssum += e;
            }
            float inv = 1.0f / ssum;
            __syncthreads();                      // done reading K

            // stage V (same region)
            for (int i = tid; i < 4 * DH_ * M_; i += 256) {
                int gg = i >> 11, d = (i >> 6) & 31, m = i & 63;
                kvs[i] = g_vp[(d * NH_ + hb + gg) * M_ + m];
            }
            __syncthreads();

            // AV + packed store, correct [b][c][n] layout (coalesced: px stride 1)
            const float* vh = kvs + cseg * (DH_ * M_);
#pragma unroll 2
            for (int d = 0; d < DH_; d++) {
                const float* vr = vh + d * M_;
                float a0 = 0.0f;
#pragma unroll
                for (int m = 0; m < M_; m++) a0 = fmaf(s[m], vr[m], a0);
                int c = d * NH_ + h;
                Y[((size_t)b * C_ + c) * NPIX + nn + px] = pack_split(a0 * inv);
            }
            __syncthreads();                      // done reading V before next hb
        }
        return;
    }

    float* p0 = (float*)(sm + 65536);
    float* p1 = (float*)(sm + 66560);
    float* p2 = (float*)(sm + 67584);
    float* sc0 = (float*)(sm + 68608);
    float* sc1 = (float*)(sm + 68864);

    if (EPI == 1) {
        const float* F = feat + ((size_t)b * 256 + cseg * 64) * NPIX + nn;
        float dsum = 0.f, msum = 0.f, fsum = 0.f;
#pragma unroll 8
        for (int cc = 0; cc < 64; cc++) {
            float v = sV[(cseg * 64 + cc) * 64 + px];
            float f = F[(size_t)cc * NPIX + px];
            dsum = fmaf(v, f, dsum);
            msum = fmaf(v, v, msum);
            fsum = fmaf(f, f, fsum);
            sV[(cseg * 64 + cc) * 64 + px] = f;
        }
        p0[cseg * 64 + px] = dsum;
        p1[cseg * 64 + px] = msum;
        p2[cseg * 64 + px] = fsum;
        __syncthreads();
        if (tid < 64) {
            float d = p0[tid] + p0[64 + tid] + p0[128 + tid] + p0[192 + tid];
            float m2 = p1[tid] + p1[64 + tid] + p1[128 + tid] + p1[192 + tid];
            float f2 = p2[tid] + p2[64 + tid] + p2[128 + tid] + p2[192 + tid];
            sc0[tid] = d / ((sqrtf(m2) + 1e-5f) * (sqrtf(f2) + 1e-5f)) + 1.0f;
        }
        __syncthreads();
        uint32_t* Y = (uint32_t*)Yv + (size_t)b * 256 * NPIX + nn;
#pragma unroll
        for (int i = 0; i < 16; i++) {
            int idx = tid + i * 256;
            int c = idx >> 4, p4 = (idx & 15) * 4;
            float4 f4 = *(float4*)&sV[c * 64 + p4];
            uint4 o;
            o.x = pack_split(f4.x * sc0[p4]);
            o.y = pack_split(f4.y * sc0[p4 + 1]);
            o.z = pack_split(f4.z * sc0[p4 + 2]);
            o.w = pack_split(f4.w * sc0[p4 + 3]);
            *(uint4*)&Y[(size_t)c * NPIX + p4] = o;
        }
    } else {
        const uint32_t* Rp = respk + ((size_t)b * 256 + cseg * 64) * NPIX + nn;
        float s = 0.f, s2 = 0.f;
#pragma unroll 8
        for (int cc = 0; cc < 64; cc++) {
            float v = sV[(cseg * 64 + cc) * 64 + px] + unpack_f(Rp[(size_t)cc * NPIX + px]);
            sV[(cseg * 64 + cc) * 64 + px] = v;
            s += v;
            s2 = fmaf(v, v, s2);
        }
        p0[cseg * 64 + px] = s;
        p1[cseg * 64 + px] = s2;
        __syncthreads();
        if (tid < 64) {
            float ss = p0[tid] + p0[64 + tid] + p0[128 + tid] + p0[192 + tid];
            float ss2 = p1[tid] + p1[64 + tid] + p1[128 + tid] + p1[192 + tid];
            float mu = ss * (1.0f / 256.0f);
            float var = ss2 * (1.0f / 256.0f) - mu * mu;
            sc0[tid] = mu;
            sc1[tid] = rsqrtf(var + 1e-5f);
        }
        __syncthreads();
        float* Y = (float*)Yv + (size_t)b * 256 * NPIX + nn;
#pragma unroll
        for (int i = 0; i < 16; i++) {
            int idx = tid + i * 256;
            int c = idx >> 4, p4 = (idx & 15) * 4;
            float gm = __ldg(gamma + c), bt = __ldg(beta + c);
            float4 v4 = *(float4*)&sV[c * 64 + p4];
            float4 o;
            o.x = (v4.x - sc0[p4])     * sc1[p4]     * gm + bt;
            o.y = (v4.y - sc0[p4 + 1]) * sc1[p4 + 1] * gm + bt;
            o.z = (v4.z - sc0[p4 + 2]) * sc1[p4 + 2] * gm + bt;
            o.w = (v4.w - sc0[p4 + 3]) * sc1[p4 + 3] * gm + bt;
            *(float4*)&Y[(size_t)c * NPIX + p4] = o;
        }
    }
}

// ---------------- host orchestration (serial, validated structure) ----------------
extern "C" void kernel_launch(void* const* d_in, const int* in_sizes, int n_in,
                              void* d_out, int out_size)
{
    const float* feature = (const float*)d_in[0];
    const float* bcw     = (const float*)d_in[1];
    const float* wq      = (const float*)d_in[2];
    const float* bq      = (const float*)d_in[3];
    const float* wk      = (const float*)d_in[4];
    const float* bk      = (const float*)d_in[5];
    const float* wv      = (const float*)d_in[6];
    const float* bv      = (const float*)d_in[7];
    const float* wm      = (const float*)d_in[8];
    const float* bm      = (const float*)d_in[9];
    const float* w1      = (const float*)d_in[10];
    const float* b1      = (const float*)d_in[11];
    const float* w2      = (const float*)d_in[12];
    const float* b2      = (const float*)d_in[13];
    const float* gamma   = (const float*)d_in[14];
    const float* beta    = (const float*)d_in[15];
    float* out = (float*)d_out;

    uint32_t *pX, *pO, *pH1;
    __nv_bfloat16 *pwqb, *pwmb, *pw1b, *pw2b;
    cudaGetSymbolAddress((void**)&pX,   g_Xpk);
    cudaGetSymbolAddress((void**)&pO,   g_Opk);
    cudaGetSymbolAddress((void**)&pH1,  g_H1pk);
    cudaGetSymbolAddress((void**)&pwqb, g_wqb);
    cudaGetSymbolAddress((void**)&pwmb, g_wmb);
    cudaGetSymbolAddress((void**)&pw1b, g_w1b);
    cudaGetSymbolAddress((void**)&pw2b, g_w2b);

    const int SMEM = 98304;
    cudaFuncSetAttribute(hgemm<3,1>, cudaFuncAttributeMaxDynamicSharedMemorySize, SMEM);
    cudaFuncSetAttribute(hgemm<0,0>, cudaFuncAttributeMaxDynamicSharedMemorySize, SMEM);
    cudaFuncSetAttribute(hgemm<1,0>, cudaFuncAttributeMaxDynamicSharedMemorySize, SMEM);
    cudaFuncSetAttribute(hgemm<2,0>, cudaFuncAttributeMaxDynamicSharedMemorySize, SMEM);

    // weight prep (tiny, deterministic; reruns each call)
    wsplit<<<256, 256>>>(wq, pwqb, 256, 256);
    wsplit<<<256, 256>>>(wm, pwmb, 256, 256);
    wsplit<<<512, 256>>>(w1, pw1b, 512, 256);
    wsplit<<<512, 256>>>(w2, pw2b, 256, 512);

    // K/V projections (batch-invariant)
    kv_proj<<<M_, C_>>>(wk, bk, wv, bv, bcw);

    const int GX = BN_TOT / 64;   // 2304

    // Q = wq @ feat + bq, fused per-thread attention -> packed X (Q never hits gmem)
    hgemm<3,1><<<dim3(GX, 1), 256, SMEM>>>(pwqb, feature, bq,
        nullptr, nullptr, nullptr, nullptr, pX, 256, 256, 0);
    // merged = wm @ X + bm, fused cosine reweight -> packed O
    hgemm<1,0><<<dim3(GX, 1), 256, SMEM>>>(pwmb, pX, bm,
        feature, nullptr, nullptr, nullptr, pO, 256, 256, 0);
    // H1 = relu(w1 @ O + b1) -> packed
    hgemm<0,0><<<dim3(GX, 2), 256, SMEM>>>(pw1b, pO, b1,
        nullptr, nullptr, nullptr, nullptr, pH1, 512, 256, 1);
    // out = LN(O + w2 @ H1 + b2) -> fp32 final output
    hgemm<2,0><<<dim3(GX, 1), 256, SMEM>>>(pw2b, pH1, b2,
        nullptr, pO, gamma, beta, out, 256, 512, 0);
}